// round 15
// baseline (speedup 1.0000x reference)
#include <cuda_runtime.h>

// Problem constants
#define D 256
#define EPS 1e-8f
#define TPB 256
#define MAIN_BLOCKS 592   // 148 SMs x 4 blocks: exactly one resident wave
#define N_NODES_MAX 100000

// Packed f32x2 helpers (sm_103a)
#define FMA2(d, a, b, c) \
    asm("fma.rn.f32x2 %0, %1, %2, %3;" : "=l"(d) : "l"(a), "l"(b), "l"(c))
#define PACK2(d, lo, hi) \
    asm("mov.b64 %0, {%1, %2};" : "=l"(d) : "f"(lo), "f"(hi))
#define UNPACK2(lo, hi, s) \
    asm("mov.b64 {%0, %1}, %2;" : "=f"(lo), "=f"(hi) : "l"(s))

// Scratch: prescaled embeddings (emb * weight_vec) and per-node inverse norms.
__device__ float g_embs[(size_t)N_NODES_MAX * D];   // ~102 MB
__device__ float g_inv[N_NODES_MAX];

// ---------------------------------------------------------------------------
// Kernel 1: prescale rows by weight_vec AND compute inverse clamped norm.
// ---------------------------------------------------------------------------
__global__ void prescale_kernel(const float* __restrict__ emb,
                                const float* __restrict__ w, int nNodes) {
    int gw   = (blockIdx.x * blockDim.x + threadIdx.x) >> 5;
    int lane = threadIdx.x & 31;
    if (gw >= nNodes) return;

    const float4* row = (const float4*)(emb + (size_t)gw * D);
    float4*       dst = (float4*)(g_embs + (size_t)gw * D);
    const float4* wv  = (const float4*)w;

    float4 e0 = row[lane],      w0 = wv[lane];
    float4 e1 = row[lane + 32], w1 = wv[lane + 32];

    float4 x0 = make_float4(e0.x * w0.x, e0.y * w0.y, e0.z * w0.z, e0.w * w0.w);
    float4 x1 = make_float4(e1.x * w1.x, e1.y * w1.y, e1.z * w1.z, e1.w * w1.w);
    dst[lane]      = x0;
    dst[lane + 32] = x1;

    float acc = 0.f;
    acc = fmaf(x0.x, x0.x, acc);
    acc = fmaf(x0.y, x0.y, acc);
    acc = fmaf(x0.z, x0.z, acc);
    acc = fmaf(x0.w, x0.w, acc);
    acc = fmaf(x1.x, x1.x, acc);
    acc = fmaf(x1.y, x1.y, acc);
    acc = fmaf(x1.z, x1.z, acc);
    acc = fmaf(x1.w, x1.w, acc);

    #pragma unroll
    for (int off = 16; off; off >>= 1)
        acc += __shfl_xor_sync(0xffffffffu, acc, off);

    if (lane == 0) {
        float n = fmaxf(sqrtf(acc), EPS);
        g_inv[gw] = 1.0f / n;
    }
}

// ---------------------------------------------------------------------------
// Kernel 2: fused edge kernel, 64 edges per warp batch (2 per lane).
//   Phase 1: 8 lanes/edge, 4 edges concurrently; L2-only row loads (__ldcg).
//   Phase 2: per lane, MLP for its 2 edges with f32x2-packed accumulators
//            (pair = the two edges), weights pre-duplicated in shared.
// ---------------------------------------------------------------------------
__global__ void __launch_bounds__(TPB, 4)
edge_kernel(const int2* __restrict__ edge,
            const float* __restrict__ W1,    // [64,2]
            const float* __restrict__ b1,    // [64]
            const float* __restrict__ W2,    // [32,64]
            const float* __restrict__ b2,    // [32]
            const float* __restrict__ Wp,    // [32]
            const float* __restrict__ bp,    // [1]
            float* __restrict__ out,
            int E, int totalWarps)
{
    __shared__ float4 s_l1[64];                               // (W1j0, W1j1, b1j, 0)
    __shared__ __align__(16) unsigned long long s_W2D[64][32]; // (w,w) dup pairs [j][i]
    __shared__ unsigned long long s_b2d[32];                   // (b,b) dup pairs
    __shared__ float  s_Wp[32];
    __shared__ float  s_bp;
    __shared__ float  s_dot[TPB / 32][64];

    int tid = threadIdx.x;
    for (int i = tid; i < 64; i += TPB)
        s_l1[i] = make_float4(W1[2*i], W1[2*i + 1], b1[i], 0.f);
    for (int i = tid; i < 2048; i += TPB) {
        int r = i & 31;        // output index i (0..31)
        int c = i >> 5;        // hidden index j (0..63)
        float wv2 = W2[r * 64 + c];
        unsigned long long p;
        PACK2(p, wv2, wv2);
        s_W2D[c][r] = p;
    }
    if (tid < 32) {
        float b = b2[tid];
        unsigned long long p;
        PACK2(p, b, b);
        s_b2d[tid] = p;
        s_Wp[tid] = Wp[tid];
    }
    if (tid == 0) s_bp = bp[0];
    __syncthreads();

    int lane  = tid & 31;
    int wid   = tid >> 5;
    int g     = lane >> 3;         // edge-group 0..3
    int s     = lane & 7;          // sublane within group
    int gwarp = (blockIdx.x * TPB + tid) >> 5;

    for (long base = (long)gwarp * 64; base < E; base += (long)totalWarps * 64) {
        // Lane owns edges base+lane and base+32+lane.
        int e0 = (int)base + lane;
        int e1 = (int)base + 32 + lane;
        int c0 = e0 < E ? e0 : E - 1;
        int c1 = e1 < E ? e1 : E - 1;
        int2 ep0 = edge[c0];
        int2 ep1 = edge[c1];
        float invp0 = g_inv[ep0.x] * g_inv[ep0.y];
        float invp1 = g_inv[ep1.x] * g_inv[ep1.y];

        // ---- Phase 1: 16 iterations, 4 edges each (64 total) ----
        #pragma unroll 4
        for (int k = 0; k < 16; k++) {
            int eb  = k * 4 + g;              // edge index within batch (0..63)
            int src = eb & 31;
            int sx = (k < 8) ? ep0.x : ep1.x;
            int sy = (k < 8) ? ep0.y : ep1.y;
            int n0 = __shfl_sync(0xffffffffu, sx, src);
            int n1 = __shfl_sync(0xffffffffu, sy, src);

            const float4* r0 = (const float4*)(g_embs + (size_t)n0 * D);
            const float4* r1 = (const float4*)(g_embs + (size_t)n1 * D);

            float acc0 = 0.f, acc1 = 0.f, acc2 = 0.f, acc3 = 0.f;
            #pragma unroll
            for (int t = 0; t < 8; t += 4) {
                float4 a0 = __ldcg(&r0[s + 8*(t+0)]), d0 = __ldcg(&r1[s + 8*(t+0)]);
                float4 a1 = __ldcg(&r0[s + 8*(t+1)]), d1 = __ldcg(&r1[s + 8*(t+1)]);
                float4 a2 = __ldcg(&r0[s + 8*(t+2)]), d2 = __ldcg(&r1[s + 8*(t+2)]);
                float4 a3 = __ldcg(&r0[s + 8*(t+3)]), d3 = __ldcg(&r1[s + 8*(t+3)]);

                acc0 = fmaf(a0.x, d0.x, acc0);
                acc0 = fmaf(a0.y, d0.y, acc0);
                acc0 = fmaf(a0.z, d0.z, acc0);
                acc0 = fmaf(a0.w, d0.w, acc0);
                acc1 = fmaf(a1.x, d1.x, acc1);
                acc1 = fmaf(a1.y, d1.y, acc1);
                acc1 = fmaf(a1.z, d1.z, acc1);
                acc1 = fmaf(a1.w, d1.w, acc1);
                acc2 = fmaf(a2.x, d2.x, acc2);
                acc2 = fmaf(a2.y, d2.y, acc2);
                acc2 = fmaf(a2.z, d2.z, acc2);
                acc2 = fmaf(a2.w, d2.w, acc2);
                acc3 = fmaf(a3.x, d3.x, acc3);
                acc3 = fmaf(a3.y, d3.y, acc3);
                acc3 = fmaf(a3.z, d3.z, acc3);
                acc3 = fmaf(a3.w, d3.w, acc3);
            }
            float acc = (acc0 + acc1) + (acc2 + acc3);

            acc += __shfl_xor_sync(0xffffffffu, acc, 4);
            acc += __shfl_xor_sync(0xffffffffu, acc, 2);
            acc += __shfl_xor_sync(0xffffffffu, acc, 1);

            if (s == 0) s_dot[wid][eb] = acc;
        }
        __syncwarp();

        float dot0 = s_dot[wid][lane];
        float dot1 = s_dot[wid][lane + 32];
        float cos0 = dot0 * invp0;
        float cos1 = dot1 * invp1;

        // ---- Phase 2: MLP for two edges, f32x2 packed across the pair ----
        float p0 = s_bp, p1 = s_bp;

        #pragma unroll
        for (int half = 0; half < 2; half++) {
            unsigned long long h2ab[16];
            #pragma unroll
            for (int i = 0; i < 16; i++) h2ab[i] = s_b2d[half * 16 + i];

            #pragma unroll 2
            for (int j = 0; j < 64; j++) {
                float4 c = s_l1[j];
                float hja = fmaxf(fmaf(cos0, c.x, fmaf(dot0, c.y, c.z)), 0.f);
                float hjb = fmaxf(fmaf(cos1, c.x, fmaf(dot1, c.y, c.z)), 0.f);
                unsigned long long hj2;
                PACK2(hj2, hja, hjb);
                const ulonglong2* colp = (const ulonglong2*)&s_W2D[j][half * 16];
                #pragma unroll
                for (int i = 0; i < 8; i++) {
                    ulonglong2 ww = colp[i];
                    FMA2(h2ab[2*i],     ww.x, hj2, h2ab[2*i]);
                    FMA2(h2ab[2*i + 1], ww.y, hj2, h2ab[2*i + 1]);
                }
            }

            #pragma unroll
            for (int i = 0; i < 16; i++) {
                float la, lb;
                UNPACK2(la, lb, h2ab[i]);
                float wp = s_Wp[half * 16 + i];
                p0 = fmaf(wp, fmaxf(la, 0.f), p0);
                p1 = fmaf(wp, fmaxf(lb, 0.f), p1);
            }
        }

        if (e0 < E) out[e0] = p0;
        if (e1 < E) out[e1] = p1;
        __syncwarp();
    }
}

// ---------------------------------------------------------------------------
// Launch
// ---------------------------------------------------------------------------
extern "C" void kernel_launch(void* const* d_in, const int* in_sizes, int n_in,
                              void* d_out, int out_size) {
    const int2*  edge = (const int2*)d_in[0];     // int32 [E,2]
    const float* emb  = (const float*)d_in[1];    // [N,256]
    const float* wv   = (const float*)d_in[2];    // [1,256]
    const float* W1   = (const float*)d_in[3];    // [64,2]
    const float* b1   = (const float*)d_in[4];    // [64]
    const float* W2   = (const float*)d_in[5];    // [32,64]
    const float* b2   = (const float*)d_in[6];    // [32]
    const float* Wp   = (const float*)d_in[7];    // [1,32]
    const float* bp   = (const float*)d_in[8];    // [1]
    float* out = (float*)d_out;

    int E      = in_sizes[0] / 2;
    int nNodes = in_sizes[1] / D;

    int preBlocks = (nNodes * 32 + TPB - 1) / TPB;
    prescale_kernel<<<preBlocks, TPB>>>(emb, wv, nNodes);

    int totalWarps = MAIN_BLOCKS * (TPB / 32);
    edge_kernel<<<MAIN_BLOCKS, TPB>>>(edge, W1, b1, W2, b2, Wp, bp,
                                      out, E, totalWarps);
}

// round 16
// speedup vs baseline: 1.1150x; 1.1150x over previous
#include <cuda_runtime.h>
#include <cuda_fp16.h>

// Problem constants
#define D 256
#define EPS 1e-8f
#define TPB 256
#define MAIN_BLOCKS 592   // 148 SMs x 4 blocks: exactly one resident wave
#define N_NODES_MAX 100000

// Scratch: prescaled embeddings (emb * weight_vec) in fp16, per-node inv norms.
__device__ __half g_embh[(size_t)N_NODES_MAX * D];   // ~51 MB
__device__ float  g_inv[N_NODES_MAX];

// ---------------------------------------------------------------------------
// Kernel 1: prescale rows by weight_vec (store fp16) AND inverse clamped norm
// (computed in fp32 before quantization).
// ---------------------------------------------------------------------------
__global__ void prescale_kernel(const float* __restrict__ emb,
                                const float* __restrict__ w, int nNodes) {
    int gw   = (blockIdx.x * blockDim.x + threadIdx.x) >> 5;
    int lane = threadIdx.x & 31;
    if (gw >= nNodes) return;

    const float4* row = (const float4*)(emb + (size_t)gw * D);
    uint2*        dst = (uint2*)(g_embh + (size_t)gw * D);  // 64 uint2 per row
    const float4* wv  = (const float4*)w;

    float4 e0 = row[lane],      w0 = wv[lane];
    float4 e1 = row[lane + 32], w1 = wv[lane + 32];

    float4 x0 = make_float4(e0.x * w0.x, e0.y * w0.y, e0.z * w0.z, e0.w * w0.w);
    float4 x1 = make_float4(e1.x * w1.x, e1.y * w1.y, e1.z * w1.z, e1.w * w1.w);

    uint2 h0, h1;
    {
        __half2 a = __floats2half2_rn(x0.x, x0.y);
        __half2 b = __floats2half2_rn(x0.z, x0.w);
        h0.x = *(unsigned*)&a; h0.y = *(unsigned*)&b;
        __half2 c = __floats2half2_rn(x1.x, x1.y);
        __half2 d = __floats2half2_rn(x1.z, x1.w);
        h1.x = *(unsigned*)&c; h1.y = *(unsigned*)&d;
    }
    dst[lane]      = h0;   // dims [4l, 4l+4)
    dst[lane + 32] = h1;   // dims [128+4l, 128+4l+4)

    float acc = 0.f;
    acc = fmaf(x0.x, x0.x, acc);
    acc = fmaf(x0.y, x0.y, acc);
    acc = fmaf(x0.z, x0.z, acc);
    acc = fmaf(x0.w, x0.w, acc);
    acc = fmaf(x1.x, x1.x, acc);
    acc = fmaf(x1.y, x1.y, acc);
    acc = fmaf(x1.z, x1.z, acc);
    acc = fmaf(x1.w, x1.w, acc);

    #pragma unroll
    for (int off = 16; off; off >>= 1)
        acc += __shfl_xor_sync(0xffffffffu, acc, off);

    if (lane == 0) {
        float n = fmaxf(sqrtf(acc), EPS);
        g_inv[gw] = 1.0f / n;
    }
}

// ---------------------------------------------------------------------------
// Kernel 2: fused edge kernel, 64 edges per warp batch (2 per lane).
//   Phase 1: 8 lanes/edge, 4 edges concurrently; fp16 rows (half the bytes),
//            HMUL2 products widened to fp32 accumulation; __ldcg (L2-only).
//   Phase 2: scalar MLP for 2 edges per lane, weights loaded once (R14 form).
// ---------------------------------------------------------------------------
__global__ void __launch_bounds__(TPB, 4)
edge_kernel(const int2* __restrict__ edge,
            const float* __restrict__ W1,    // [64,2]
            const float* __restrict__ b1,    // [64]
            const float* __restrict__ W2,    // [32,64]
            const float* __restrict__ b2,    // [32]
            const float* __restrict__ Wp,    // [32]
            const float* __restrict__ bp,    // [1]
            float* __restrict__ out,
            int E, int totalWarps)
{
    __shared__ float4 s_l1[64];           // (W1[j][0], W1[j][1], b1[j], 0)
    __shared__ float  s_W2T[64][32];      // W2 transposed: [j][i]
    __shared__ float  s_b2[32];
    __shared__ float  s_Wp[32];
    __shared__ float  s_bp;
    __shared__ float  s_dot[TPB / 32][64];

    int tid = threadIdx.x;
    for (int i = tid; i < 64; i += TPB)
        s_l1[i] = make_float4(W1[2*i], W1[2*i + 1], b1[i], 0.f);
    for (int i = tid; i < 2048; i += TPB) {
        int r = i & 31;        // output index i (0..31)
        int c = i >> 5;        // hidden index j (0..63)
        s_W2T[c][r] = W2[r * 64 + c];
    }
    if (tid < 32) { s_b2[tid] = b2[tid]; s_Wp[tid] = Wp[tid]; }
    if (tid == 0) s_bp = bp[0];
    __syncthreads();

    int lane  = tid & 31;
    int wid   = tid >> 5;
    int g     = lane >> 3;         // edge-group 0..3
    int s     = lane & 7;          // sublane within group
    int gwarp = (blockIdx.x * TPB + tid) >> 5;

    for (long base = (long)gwarp * 64; base < E; base += (long)totalWarps * 64) {
        // Lane owns edges base+lane and base+32+lane.
        int e0 = (int)base + lane;
        int e1 = (int)base + 32 + lane;
        int c0 = e0 < E ? e0 : E - 1;
        int c1 = e1 < E ? e1 : E - 1;
        int2 ep0 = edge[c0];
        int2 ep1 = edge[c1];
        float invp0 = g_inv[ep0.x] * g_inv[ep0.y];
        float invp1 = g_inv[ep1.x] * g_inv[ep1.y];

        // ---- Phase 1: 16 iterations, 4 edges each (64 total) ----
        // Lane s covers dims [32s, 32s+32) = uint4 (8 halves) idx [4s, 4s+4).
        #pragma unroll 4
        for (int k = 0; k < 16; k++) {
            int eb  = k * 4 + g;              // edge index within batch (0..63)
            int src = eb & 31;
            int sx = (k < 8) ? ep0.x : ep1.x;
            int sy = (k < 8) ? ep0.y : ep1.y;
            int n0 = __shfl_sync(0xffffffffu, sx, src);
            int n1 = __shfl_sync(0xffffffffu, sy, src);

            const uint4* r0 = (const uint4*)(g_embh + (size_t)n0 * D);
            const uint4* r1 = (const uint4*)(g_embh + (size_t)n1 * D);

            float acc0 = 0.f, acc1 = 0.f, acc2 = 0.f, acc3 = 0.f;
            #pragma unroll
            for (int t = 0; t < 4; t++) {
                uint4 A = __ldcg(&r0[4*s + t]);
                uint4 B = __ldcg(&r1[4*s + t]);
                __half2 p0 = __hmul2(*(__half2*)&A.x, *(__half2*)&B.x);
                __half2 p1 = __hmul2(*(__half2*)&A.y, *(__half2*)&B.y);
                __half2 p2 = __hmul2(*(__half2*)&A.z, *(__half2*)&B.z);
                __half2 p3 = __hmul2(*(__half2*)&A.w, *(__half2*)&B.w);
                float2 f0 = __half22float2(p0);
                float2 f1 = __half22float2(p1);
                float2 f2 = __half22float2(p2);
                float2 f3 = __half22float2(p3);
                acc0 += f0.x + f0.y;
                acc1 += f1.x + f1.y;
                acc2 += f2.x + f2.y;
                acc3 += f3.x + f3.y;
            }
            float acc = (acc0 + acc1) + (acc2 + acc3);

            acc += __shfl_xor_sync(0xffffffffu, acc, 4);
            acc += __shfl_xor_sync(0xffffffffu, acc, 2);
            acc += __shfl_xor_sync(0xffffffffu, acc, 1);

            if (s == 0) s_dot[wid][eb] = acc;
        }
        __syncwarp();

        float dot0 = s_dot[wid][lane];
        float dot1 = s_dot[wid][lane + 32];
        float cos0 = dot0 * invp0;
        float cos1 = dot1 * invp1;

        // ---- Phase 2: MLP for two edges, weights loaded once (scalar) ----
        float p0 = s_bp, p1 = s_bp;

        #pragma unroll
        for (int half = 0; half < 2; half++) {
            float h2a[16], h2b[16];
            #pragma unroll
            for (int i = 0; i < 16; i++) {
                float b = s_b2[half * 16 + i];
                h2a[i] = b;
                h2b[i] = b;
            }

            #pragma unroll 2
            for (int j = 0; j < 64; j++) {
                float4 c = s_l1[j];
                float hja = fmaxf(fmaf(cos0, c.x, fmaf(dot0, c.y, c.z)), 0.f);
                float hjb = fmaxf(fmaf(cos1, c.x, fmaf(dot1, c.y, c.z)), 0.f);
                const float* col = &s_W2T[j][half * 16];
                #pragma unroll
                for (int i = 0; i < 16; i++) {
                    float wv2 = col[i];
                    h2a[i] = fmaf(wv2, hja, h2a[i]);
                    h2b[i] = fmaf(wv2, hjb, h2b[i]);
                }
            }

            #pragma unroll
            for (int i = 0; i < 16; i++) {
                float wp = s_Wp[half * 16 + i];
                p0 = fmaf(wp, fmaxf(h2a[i], 0.f), p0);
                p1 = fmaf(wp, fmaxf(h2b[i], 0.f), p1);
            }
        }

        if (e0 < E) out[e0] = p0;
        if (e1 < E) out[e1] = p1;
        __syncwarp();
    }
}

// ---------------------------------------------------------------------------
// Launch
// ---------------------------------------------------------------------------
extern "C" void kernel_launch(void* const* d_in, const int* in_sizes, int n_in,
                              void* d_out, int out_size) {
    const int2*  edge = (const int2*)d_in[0];     // int32 [E,2]
    const float* emb  = (const float*)d_in[1];    // [N,256]
    const float* wv   = (const float*)d_in[2];    // [1,256]
    const float* W1   = (const float*)d_in[3];    // [64,2]
    const float* b1   = (const float*)d_in[4];    // [64]
    const float* W2   = (const float*)d_in[5];    // [32,64]
    const float* b2   = (const float*)d_in[6];    // [32]
    const float* Wp   = (const float*)d_in[7];    // [1,32]
    const float* bp   = (const float*)d_in[8];    // [1]
    float* out = (float*)d_out;

    int E      = in_sizes[0] / 2;
    int nNodes = in_sizes[1] / D;

    int preBlocks = (nNodes * 32 + TPB - 1) / TPB;
    prescale_kernel<<<preBlocks, TPB>>>(emb, wv, nNodes);

    int totalWarps = MAIN_BLOCKS * (TPB / 32);
    edge_kernel<<<MAIN_BLOCKS, TPB>>>(edge, W1, b1, W2, b2, Wp, bp,
                                      out, E, totalWarps);
}

// round 17
// speedup vs baseline: 1.5218x; 1.3649x over previous
#include <cuda_runtime.h>
#include <cuda_fp16.h>

// Problem constants
#define D 256
#define EPS 1e-8f
#define TPB 256
#define MAIN_BLOCKS 592   // 148 SMs x 4 blocks: exactly one resident wave
#define N_NODES_MAX 100000

// Scratch: prescaled embeddings (emb * weight_vec) in fp16, per-node inv norms.
__device__ __half g_embh[(size_t)N_NODES_MAX * D];   // ~51 MB
__device__ float  g_inv[N_NODES_MAX];

// ---------------------------------------------------------------------------
// Kernel 1: prescale rows by weight_vec (store fp16) AND inverse clamped norm
// (computed in fp32 before quantization).
// ---------------------------------------------------------------------------
__global__ void prescale_kernel(const float* __restrict__ emb,
                                const float* __restrict__ w, int nNodes) {
    int gw   = (blockIdx.x * blockDim.x + threadIdx.x) >> 5;
    int lane = threadIdx.x & 31;
    if (gw >= nNodes) return;

    const float4* row = (const float4*)(emb + (size_t)gw * D);
    uint2*        dst = (uint2*)(g_embh + (size_t)gw * D);  // 64 uint2 per row
    const float4* wv  = (const float4*)w;

    float4 e0 = row[lane],      w0 = wv[lane];
    float4 e1 = row[lane + 32], w1 = wv[lane + 32];

    float4 x0 = make_float4(e0.x * w0.x, e0.y * w0.y, e0.z * w0.z, e0.w * w0.w);
    float4 x1 = make_float4(e1.x * w1.x, e1.y * w1.y, e1.z * w1.z, e1.w * w1.w);

    uint2 h0, h1;
    {
        __half2 a = __floats2half2_rn(x0.x, x0.y);
        __half2 b = __floats2half2_rn(x0.z, x0.w);
        h0.x = *(unsigned*)&a; h0.y = *(unsigned*)&b;
        __half2 c = __floats2half2_rn(x1.x, x1.y);
        __half2 d = __floats2half2_rn(x1.z, x1.w);
        h1.x = *(unsigned*)&c; h1.y = *(unsigned*)&d;
    }
    dst[lane]      = h0;   // dims [4l, 4l+4)
    dst[lane + 32] = h1;   // dims [128+4l, 128+4l+4)

    float acc = 0.f;
    acc = fmaf(x0.x, x0.x, acc);
    acc = fmaf(x0.y, x0.y, acc);
    acc = fmaf(x0.z, x0.z, acc);
    acc = fmaf(x0.w, x0.w, acc);
    acc = fmaf(x1.x, x1.x, acc);
    acc = fmaf(x1.y, x1.y, acc);
    acc = fmaf(x1.z, x1.z, acc);
    acc = fmaf(x1.w, x1.w, acc);

    #pragma unroll
    for (int off = 16; off; off >>= 1)
        acc += __shfl_xor_sync(0xffffffffu, acc, off);

    if (lane == 0) {
        float n = fmaxf(sqrtf(acc), EPS);
        g_inv[gw] = 1.0f / n;
    }
}

// ---------------------------------------------------------------------------
// Kernel 2: fused edge kernel, 64 edges per warp batch (2 per lane).
//   Phase 1: 8 lanes/edge, 4 edges concurrently; fp16 rows with CONTIGUOUS
//            per-group loads (lane s -> uint4 idx s+8t: one 128B line per
//            group per instruction); HMUL2 -> fp32 accumulate; __ldcg.
//   Phase 2: scalar MLP for 2 edges per lane, weights loaded once.
// ---------------------------------------------------------------------------
__global__ void __launch_bounds__(TPB, 4)
edge_kernel(const int2* __restrict__ edge,
            const float* __restrict__ W1,    // [64,2]
            const float* __restrict__ b1,    // [64]
            const float* __restrict__ W2,    // [32,64]
            const float* __restrict__ b2,    // [32]
            const float* __restrict__ Wp,    // [32]
            const float* __restrict__ bp,    // [1]
            float* __restrict__ out,
            int E, int totalWarps)
{
    __shared__ float4 s_l1[64];           // (W1[j][0], W1[j][1], b1[j], 0)
    __shared__ float  s_W2T[64][32];      // W2 transposed: [j][i]
    __shared__ float  s_b2[32];
    __shared__ float  s_Wp[32];
    __shared__ float  s_bp;
    __shared__ float  s_dot[TPB / 32][64];

    int tid = threadIdx.x;
    for (int i = tid; i < 64; i += TPB)
        s_l1[i] = make_float4(W1[2*i], W1[2*i + 1], b1[i], 0.f);
    for (int i = tid; i < 2048; i += TPB) {
        int r = i & 31;        // output index i (0..31)
        int c = i >> 5;        // hidden index j (0..63)
        s_W2T[c][r] = W2[r * 64 + c];
    }
    if (tid < 32) { s_b2[tid] = b2[tid]; s_Wp[tid] = Wp[tid]; }
    if (tid == 0) s_bp = bp[0];
    __syncthreads();

    int lane  = tid & 31;
    int wid   = tid >> 5;
    int g     = lane >> 3;         // edge-group 0..3
    int s     = lane & 7;          // sublane within group
    int gwarp = (blockIdx.x * TPB + tid) >> 5;

    for (long base = (long)gwarp * 64; base < E; base += (long)totalWarps * 64) {
        // Lane owns edges base+lane and base+32+lane.
        int e0 = (int)base + lane;
        int e1 = (int)base + 32 + lane;
        int c0 = e0 < E ? e0 : E - 1;
        int c1 = e1 < E ? e1 : E - 1;
        int2 ep0 = edge[c0];
        int2 ep1 = edge[c1];
        float invp0 = g_inv[ep0.x] * g_inv[ep0.y];
        float invp1 = g_inv[ep1.x] * g_inv[ep1.y];

        // ---- Phase 1: 16 iterations, 4 edges each (64 total) ----
        // fp16 row = 32 uint4 (512B). Lane s loads uint4 idx s+8t (t=0..3):
        // each instruction -> 8 contiguous 16B per group = one 128B line.
        #pragma unroll 4
        for (int k = 0; k < 16; k++) {
            int eb  = k * 4 + g;              // edge index within batch (0..63)
            int src = eb & 31;
            int sx = (k < 8) ? ep0.x : ep1.x;
            int sy = (k < 8) ? ep0.y : ep1.y;
            int n0 = __shfl_sync(0xffffffffu, sx, src);
            int n1 = __shfl_sync(0xffffffffu, sy, src);

            const uint4* r0 = (const uint4*)(g_embh + (size_t)n0 * D);
            const uint4* r1 = (const uint4*)(g_embh + (size_t)n1 * D);

            float acc0 = 0.f, acc1 = 0.f, acc2 = 0.f, acc3 = 0.f;
            #pragma unroll
            for (int t = 0; t < 4; t++) {
                uint4 A = __ldcg(&r0[s + 8*t]);
                uint4 B = __ldcg(&r1[s + 8*t]);
                __half2 p0 = __hmul2(*(__half2*)&A.x, *(__half2*)&B.x);
                __half2 p1 = __hmul2(*(__half2*)&A.y, *(__half2*)&B.y);
                __half2 p2 = __hmul2(*(__half2*)&A.z, *(__half2*)&B.z);
                __half2 p3 = __hmul2(*(__half2*)&A.w, *(__half2*)&B.w);
                float2 f0 = __half22float2(p0);
                float2 f1 = __half22float2(p1);
                float2 f2 = __half22float2(p2);
                float2 f3 = __half22float2(p3);
                acc0 += f0.x + f0.y;
                acc1 += f1.x + f1.y;
                acc2 += f2.x + f2.y;
                acc3 += f3.x + f3.y;
            }
            float acc = (acc0 + acc1) + (acc2 + acc3);

            acc += __shfl_xor_sync(0xffffffffu, acc, 4);
            acc += __shfl_xor_sync(0xffffffffu, acc, 2);
            acc += __shfl_xor_sync(0xffffffffu, acc, 1);

            if (s == 0) s_dot[wid][eb] = acc;
        }
        __syncwarp();

        float dot0 = s_dot[wid][lane];
        float dot1 = s_dot[wid][lane + 32];
        float cos0 = dot0 * invp0;
        float cos1 = dot1 * invp1;

        // ---- Phase 2: MLP for two edges, weights loaded once (scalar) ----
        float p0 = s_bp, p1 = s_bp;

        #pragma unroll
        for (int half = 0; half < 2; half++) {
            float h2a[16], h2b[16];
            #pragma unroll
            for (int i = 0; i < 16; i++) {
                float b = s_b2[half * 16 + i];
                h2a[i] = b;
                h2b[i] = b;
            }

            #pragma unroll 2
            for (int j = 0; j < 64; j++) {
                float4 c = s_l1[j];
                float hja = fmaxf(fmaf(cos0, c.x, fmaf(dot0, c.y, c.z)), 0.f);
                float hjb = fmaxf(fmaf(cos1, c.x, fmaf(dot1, c.y, c.z)), 0.f);
                const float* col = &s_W2T[j][half * 16];
                #pragma unroll
                for (int i = 0; i < 16; i++) {
                    float wv2 = col[i];
                    h2a[i] = fmaf(wv2, hja, h2a[i]);
                    h2b[i] = fmaf(wv2, hjb, h2b[i]);
                }
            }

            #pragma unroll
            for (int i = 0; i < 16; i++) {
                float wp = s_Wp[half * 16 + i];
                p0 = fmaf(wp, fmaxf(h2a[i], 0.f), p0);
                p1 = fmaf(wp, fmaxf(h2b[i], 0.f), p1);
            }
        }

        if (e0 < E) out[e0] = p0;
        if (e1 < E) out[e1] = p1;
        __syncwarp();
    }
}

// ---------------------------------------------------------------------------
// Launch
// ---------------------------------------------------------------------------
extern "C" void kernel_launch(void* const* d_in, const int* in_sizes, int n_in,
                              void* d_out, int out_size) {
    const int2*  edge = (const int2*)d_in[0];     // int32 [E,2]
    const float* emb  = (const float*)d_in[1];    // [N,256]
    const float* wv   = (const float*)d_in[2];    // [1,256]
    const float* W1   = (const float*)d_in[3];    // [64,2]
    const float* b1   = (const float*)d_in[4];    // [64]
    const float* W2   = (const float*)d_in[5];    // [32,64]
    const float* b2   = (const float*)d_in[6];    // [32]
    const float* Wp   = (const float*)d_in[7];    // [1,32]
    const float* bp   = (const float*)d_in[8];    // [1]
    float* out = (float*)d_out;

    int E      = in_sizes[0] / 2;
    int nNodes = in_sizes[1] / D;

    int preBlocks = (nNodes * 32 + TPB - 1) / TPB;
    prescale_kernel<<<preBlocks, TPB>>>(emb, wv, nNodes);

    int totalWarps = MAIN_BLOCKS * (TPB / 32);
    edge_kernel<<<MAIN_BLOCKS, TPB>>>(edge, W1, b1, W2, b2, Wp, bp,
                                      out, E, totalWarps);
}